// round 1
// baseline (speedup 1.0000x reference)
#include <cuda_runtime.h>

#define N_BINS 85
#define NBLOCKS 1184            // 8 * 148 SMs
#define GROUPS_PER_BLOCK 3
#define ACTIVE_THREADS (GROUPS_PER_BLOCK * N_BINS)   // 255
#define BLOCK_THREADS 256
#define TOTAL_GROUPS (NBLOCKS * GROUPS_PER_BLOCK)    // 3552
#define S2_ROWS 12                                   // 12*85 = 1020 active threads in stage2

// Per-block column partial sums of (input - target). No dynamic allocation allowed.
__device__ float g_part[NBLOCKS * N_BINS];

// ---------------------------------------------------------------------------
// Stage 1: grid-stride column reduction over "super-rows" (4 rows = 85 float4s)
// Thread t in block: group g = bx*3 + t/85, position p = t%85.
// Its float4 covers fixed columns (4p+k) mod 85 for k=0..3.
// ---------------------------------------------------------------------------
__global__ void __launch_bounds__(BLOCK_THREADS, 8)
emd_stage1(const float4* __restrict__ in4, const float4* __restrict__ tg4,
           const float* __restrict__ in, const float* __restrict__ tg,
           int nsuper, int total_elems)
{
    __shared__ float sd[N_BINS];
    int t = threadIdx.x;
    if (t < N_BINS) sd[t] = 0.0f;

    float a0 = 0.f, a1 = 0.f, a2 = 0.f, a3 = 0.f;
    int p = 0;
    if (t < ACTIVE_THREADS) {
        int g = blockIdx.x * GROUPS_PER_BLOCK + (t / N_BINS);
        p = t % N_BINS;
        #pragma unroll 4
        for (int s = g; s < nsuper; s += TOTAL_GROUPS) {
            int idx = s * N_BINS + p;      // float4 index; max ~10.6M, fits int
            float4 a = in4[idx];
            float4 b = tg4[idx];
            a0 += a.x - b.x;
            a1 += a.y - b.y;
            a2 += a.z - b.z;
            a3 += a.w - b.w;
        }
    }
    __syncthreads();
    if (t < ACTIVE_THREADS) {
        int c0 = (4 * p) % N_BINS;
        int c1 = (4 * p + 1) % N_BINS;
        int c2 = (4 * p + 2) % N_BINS;
        int c3 = (4 * p + 3) % N_BINS;
        atomicAdd(&sd[c0], a0);
        atomicAdd(&sd[c1], a1);
        atomicAdd(&sd[c2], a2);
        atomicAdd(&sd[c3], a3);
    }
    // Tail rows (B % 4 != 0): handled scalar by block 0. (B=500000 -> empty.)
    if (blockIdx.x == 0) {
        int tail_start = nsuper * (4 * N_BINS);
        for (int i = tail_start + t; i < total_elems; i += BLOCK_THREADS) {
            atomicAdd(&sd[i % N_BINS], in[i] - tg[i]);
        }
    }
    __syncthreads();
    if (t < N_BINS) g_part[blockIdx.x * N_BINS + t] = sd[t];
}

// ---------------------------------------------------------------------------
// Stage 2: reduce NBLOCKS x 85 partials, abs, cumsum-weighted sum -> out[0]
// ---------------------------------------------------------------------------
__global__ void emd_stage2(float* __restrict__ out)
{
    __shared__ float s2[S2_ROWS][N_BINS];
    __shared__ float d[N_BINS];
    int t = threadIdx.x;

    if (t < S2_ROWS * N_BINS) {
        int c = t % N_BINS;
        int r = t / N_BINS;
        float acc = 0.f;
        #pragma unroll 4
        for (int b = r; b < NBLOCKS; b += S2_ROWS) {
            acc += g_part[b * N_BINS + c];   // lanes read consecutive columns: coalesced
        }
        s2[r][c] = acc;
    }
    __syncthreads();
    if (t < N_BINS) {
        float tot = 0.f;
        #pragma unroll
        for (int r = 0; r < S2_ROWS; r++) tot += s2[r][t];
        d[t] = fabsf(tot);
    }
    __syncthreads();
    if (t == 0) {
        float cum = 0.f, loss = 0.f;
        #pragma unroll
        for (int j = 0; j < N_BINS; j++) {
            cum += d[j];
            loss += cum / (float)(j + 1);
        }
        out[0] = loss * 0.1f;
    }
}

extern "C" void kernel_launch(void* const* d_in, const int* in_sizes, int n_in,
                              void* d_out, int out_size)
{
    const float* in = (const float*)d_in[0];
    const float* tg = (const float*)d_in[1];
    int total = in_sizes[0];            // 500000 * 85
    int B = total / N_BINS;
    int nsuper = B / 4;

    emd_stage1<<<NBLOCKS, BLOCK_THREADS>>>((const float4*)in, (const float4*)tg,
                                           in, tg, nsuper, total);
    emd_stage2<<<1, 1024>>>((float*)d_out);
}

// round 2
// speedup vs baseline: 1.1734x; 1.1734x over previous
#include <cuda_runtime.h>

#define N_BINS 85
#define NBLOCKS 1184            // 8 * 148 SMs
#define GROUPS_PER_BLOCK 3
#define ACTIVE_THREADS (GROUPS_PER_BLOCK * N_BINS)   // 255
#define BLOCK_THREADS 256
#define TOTAL_GROUPS (NBLOCKS * GROUPS_PER_BLOCK)    // 3552

// Global accumulator (zero at module load; reset by the last block each call
// so graph replays are deterministic). No dynamic allocation allowed.
__device__ float g_acc[N_BINS];
__device__ unsigned int g_count;

// ---------------------------------------------------------------------------
// Fused: grid-stride column reduction over "super-rows" (4 rows = 85 float4s),
// block partials -> global float atomics -> last-finishing block does the
// abs/cumsum/weighted-sum epilogue and resets state.
//
// Thread t: group g = bx*3 + t/85, float4 position p = t%85.
// Its float4 covers fixed columns (4p+k) mod 85 for k=0..3.
// ---------------------------------------------------------------------------
__global__ void __launch_bounds__(BLOCK_THREADS, 8)
emd_fused(const float4* __restrict__ in4, const float4* __restrict__ tg4,
          const float* __restrict__ in, const float* __restrict__ tg,
          int nsuper, int total_elems, float* __restrict__ out)
{
    __shared__ float sd[N_BINS];
    __shared__ int islast;
    int t = threadIdx.x;
    if (t < N_BINS) sd[t] = 0.0f;

    float a0 = 0.f, a1 = 0.f, a2 = 0.f, a3 = 0.f;
    int p = 0;
    if (t < ACTIVE_THREADS) {
        int g = blockIdx.x * GROUPS_PER_BLOCK + (t / N_BINS);
        p = t % N_BINS;
        #pragma unroll 4
        for (int s = g; s < nsuper; s += TOTAL_GROUPS) {
            int idx = s * N_BINS + p;          // float4 index; ~10.6M max, fits int
            float4 a = in4[idx];
            float4 b = tg4[idx];
            a0 += a.x - b.x;
            a1 += a.y - b.y;
            a2 += a.z - b.z;
            a3 += a.w - b.w;
        }
    }
    __syncthreads();
    if (t < ACTIVE_THREADS) {
        int c0 = (4 * p) % N_BINS;
        int c1 = (4 * p + 1) % N_BINS;
        int c2 = (4 * p + 2) % N_BINS;
        int c3 = (4 * p + 3) % N_BINS;
        atomicAdd(&sd[c0], a0);
        atomicAdd(&sd[c1], a1);
        atomicAdd(&sd[c2], a2);
        atomicAdd(&sd[c3], a3);
    }
    // Tail rows (B % 4 != 0): scalar, block 0 only. (B=500000 -> empty loop.)
    if (blockIdx.x == 0) {
        int tail_start = nsuper * (4 * N_BINS);
        for (int i = tail_start + t; i < total_elems; i += BLOCK_THREADS) {
            atomicAdd(&sd[i % N_BINS], in[i] - tg[i]);
        }
    }
    __syncthreads();

    // Publish block partials via L2 float atomics (85 distinct addresses).
    if (t < N_BINS) atomicAdd(&g_acc[t], sd[t]);
    __threadfence();          // release: my atomics visible before my ticket
    __syncthreads();          // all 85 publisher threads passed the fence
    if (t == 0) {
        unsigned int ticket = atomicAdd(&g_count, 1u);
        islast = (ticket == NBLOCKS - 1u);
    }
    __syncthreads();

    if (islast) {
        __shared__ float d[N_BINS];
        __threadfence();      // acquire: order reads after observing final ticket
        if (t < N_BINS) {
            float v = *((volatile float*)&g_acc[t]);
            g_acc[t] = 0.0f;                   // reset for next graph replay
            d[t] = fabsf(v);
        }
        __syncthreads();
        if (t == 0) {
            float cum = 0.f, loss = 0.f;
            #pragma unroll
            for (int j = 0; j < N_BINS; j++) {
                cum += d[j];
                loss += cum / (float)(j + 1);
            }
            out[0] = loss * 0.1f;
            g_count = 0u;                      // reset ticket counter
        }
    }
}

extern "C" void kernel_launch(void* const* d_in, const int* in_sizes, int n_in,
                              void* d_out, int out_size)
{
    const float* in = (const float*)d_in[0];
    const float* tg = (const float*)d_in[1];
    int total = in_sizes[0];            // 500000 * 85
    int B = total / N_BINS;
    int nsuper = B / 4;

    emd_fused<<<NBLOCKS, BLOCK_THREADS>>>((const float4*)in, (const float4*)tg,
                                          in, tg, nsuper, total, (float*)d_out);
}